// round 2
// baseline (speedup 1.0000x reference)
#include <cuda_runtime.h>

// DilatedSparseRnnStack on GB300.
// Design: 128 persistent CTAs = 4 layers x 2 column-halves x 16 batch-groups.
// Each CTA keeps its 256x192 fp32 weight half in SMEM and streams the T=256
// recurrence; layers run concurrently, skewed by one step, communicating
// h/out/C through __device__ global history buffers with fence+flag sync.
// A final small kernel does the 64x64 output projection.

#define TT   256      // timesteps
#define BB   256      // batch
#define KD   192      // 64 x + 64 prevH + 64 dH
#define RH   256      // gate rows per half (512 total)
#define BS   16       // batch per group
#define NG   16       // batch groups
#define SMEM_FLOATS (KD*RH + RH + 4096)
#define SMEM_BYTES  (SMEM_FLOATS * 4)

// history buffers (written before read within a run; no reset needed)
__device__ float g_h[4][TT][BB][64];     // h per layer
__device__ float g_C[4][TT][BB][128];    // cell state per layer
__device__ float g_o[4][TT][BB][64];     // layer outputs
__device__ int   g_hf[4][NG];            // h progress flags
__device__ int   g_of[4][NG];            // out progress flags

__device__ __forceinline__ float sigm(float x){
    return __fdividef(1.f, 1.f + __expf(-x));
}
__device__ __forceinline__ float tanh_f(float x){
    float e = __expf(2.f * x);
    return 1.f - __fdividef(2.f, e + 1.f);
}

extern "C" __global__ void reset_kernel(){
    int i = threadIdx.x;
    if (i < 4*NG){ ((int*)g_hf)[i] = 0; ((int*)g_of)[i] = 0; }
}

extern "C" __global__ void __launch_bounds__(256,1)
rnn_kernel(const float* __restrict__ X, const float* __restrict__ W,
           const float* __restrict__ Bv)
{
    extern __shared__ float sm[];
    float* sW  = sm;                 // [k*RH + r]  transposed weights
    float* sB  = sm + KD*RH;         // [RH] bias
    float* sXH = sB + RH;            // xh[b*KD + k]; later gates[b*RH + r]

    const int tid  = threadIdx.x;
    const int bid  = blockIdx.x;
    const int l    = bid >> 5;          // layer 0..3
    const int half = (bid >> 4) & 1;    // 0: states 0..63 (out), 1: states 64..127 (h)
    const int g    = bid & 15;          // batch group
    const int G0   = g * BS;
    const int d    = (l==0) ? 1 : ((l==1) ? 3 : ((l==2) ? 6 : 12));

    // ---- load this half's 256 rows of W[l], transposed into SMEM ----
    // local row r (0..255)  <->  global row  (r/64)*128 + half*64 + (r%64)
    const float* Wl = W + (size_t)l * 512 * KD;
    for (int idx = tid; idx < RH*KD; idx += 256){
        int r = idx / KD;
        int k = idx - r*KD;
        int grow = ((r>>6)<<7) + (half<<6) + (r&63);
        sW[k*RH + r] = Wl[(size_t)grow*KD + k];
    }
    {
        int grow = ((tid>>6)<<7) + (half<<6) + (tid&63);
        sB[tid] = Bv[l*512 + grow];
    }
    __syncthreads();

    // matvec tile: thread computes rows rg..rg+3, batch bg..bg+3
    const int rg  = (tid & 63) << 2;
    const int bg  = (tid >> 6) << 2;
    // epilogue tile: thread owns batch eb, local states es0..es0+3 (persistent C)
    const int eb  = tid >> 4;
    const int es0 = (tid & 15) << 2;

    float cP[4] = {0.f, 0.f, 0.f, 0.f};

    for (int t = 0; t < TT; ++t){
        // ---- wait for producers ----
        if (tid == 0){
            if (l > 0){
                volatile int* fp = &g_of[l-1][g];
                while (*fp < t+1) {}
            }
            if (half == 0 && t > 0){   // out-half needs peer h(t-1)
                volatile int* fp = &g_hf[l][g];
                while (*fp < t) {}
            }
            __threadfence();
        }
        __syncthreads();

        // ---- stage xh[b][k] = [ x_t | prevH | dH ] ----
        const float* srcX = (l==0) ? (X + ((size_t)t*BB + G0)*64)
                                   : &g_o[l-1][t][G0][0];
        const float* srcP = (t > 0)  ? &g_h[l][t-1][G0][0] : (const float*)0;
        const float* srcD = (t >= d) ? &g_h[l][t-d][G0][0] : srcP;
        #pragma unroll
        for (int it = 0; it < 12; ++it){
            int e   = it*256 + tid;        // 0..3071
            int sec = e >> 10;             // 0:x 1:prevH 2:dH
            int e2  = e & 1023;
            int b   = e2 >> 6;
            int c   = e2 & 63;
            const float* s = (sec == 0) ? srcX : ((sec == 1) ? srcP : srcD);
            float v = s ? s[b*64 + c] : 0.f;
            sXH[b*KD + sec*64 + c] = v;
        }
        __syncthreads();

        // ---- matvec: acc[i][j] = sum_k W[rg+i][k] * xh[bg+j][k] ----
        float acc[4][4];
        #pragma unroll
        for (int i = 0; i < 4; i++)
            #pragma unroll
            for (int j = 0; j < 4; j++) acc[i][j] = 0.f;

        const float* xb = sXH + bg*KD;
        #pragma unroll 4
        for (int k = 0; k < KD; ++k){
            float4 wv = *(const float4*)(sW + (k<<8) + rg);
            float x0 = xb[k];
            float x1 = xb[KD   + k];
            float x2 = xb[2*KD + k];
            float x3 = xb[3*KD + k];
            acc[0][0] = fmaf(wv.x, x0, acc[0][0]);
            acc[1][0] = fmaf(wv.y, x0, acc[1][0]);
            acc[2][0] = fmaf(wv.z, x0, acc[2][0]);
            acc[3][0] = fmaf(wv.w, x0, acc[3][0]);
            acc[0][1] = fmaf(wv.x, x1, acc[0][1]);
            acc[1][1] = fmaf(wv.y, x1, acc[1][1]);
            acc[2][1] = fmaf(wv.z, x1, acc[2][1]);
            acc[3][1] = fmaf(wv.w, x1, acc[3][1]);
            acc[0][2] = fmaf(wv.x, x2, acc[0][2]);
            acc[1][2] = fmaf(wv.y, x2, acc[1][2]);
            acc[2][2] = fmaf(wv.z, x2, acc[2][2]);
            acc[3][2] = fmaf(wv.w, x2, acc[3][2]);
            acc[0][3] = fmaf(wv.x, x3, acc[0][3]);
            acc[1][3] = fmaf(wv.y, x3, acc[1][3]);
            acc[2][3] = fmaf(wv.z, x3, acc[2][3]);
            acc[3][3] = fmaf(wv.w, x3, acc[3][3]);
        }
        __syncthreads();   // xh fully consumed -> reuse region for gates

        // gates[b][r]
        #pragma unroll
        for (int j = 0; j < 4; j++){
            *(float4*)(sXH + (bg+j)*RH + rg) =
                make_float4(acc[0][j], acc[1][j], acc[2][j], acc[3][j]);
        }
        __syncthreads();

        // ---- elementwise gates + recurrence ----
        const float* gb = sXH + eb*RH;
        float4 q0 = *(const float4*)(gb +         es0);
        float4 q1 = *(const float4*)(gb +  64  +  es0);
        float4 q2 = *(const float4*)(gb + 128  +  es0);
        float4 q3 = *(const float4*)(gb + 192  +  es0);
        float4 b0 = *(const float4*)(sB +         es0);
        float4 b1 = *(const float4*)(sB +  64  +  es0);
        float4 b2 = *(const float4*)(sB + 128  +  es0);
        float4 b3 = *(const float4*)(sB + 192  +  es0);
        float4 dC = make_float4(0.f, 0.f, 0.f, 0.f);
        if (t >= d) dC = *(const float4*)(&g_C[l][t-d][G0+eb][(half<<6) + es0]);

        float nc[4], wh[4];
        #define LANE(J, GA, GB, GC, GD, BA, BBV, BC, BD, DCV)                 \
        {                                                                     \
            float f  = sigm((GA) + (BA) + 1.f);                               \
            float ns = tanh_f((GB) + (BBV));                                  \
            float al = sigm((GC) + (BC));                                     \
            float oo = sigm((GD) + (BD));                                     \
            float wc = (t >= d) ? (al*cP[J] + (1.f-al)*(DCV)) : cP[J];        \
            float c2 = (t > 0)  ? (f*wc + (1.f-f)*ns) : ns;                   \
            nc[J] = c2; wh[J] = oo*c2; cP[J] = c2;                            \
        }
        LANE(0, q0.x, q1.x, q2.x, q3.x, b0.x, b1.x, b2.x, b3.x, dC.x)
        LANE(1, q0.y, q1.y, q2.y, q3.y, b0.y, b1.y, b2.y, b3.y, dC.y)
        LANE(2, q0.z, q1.z, q2.z, q3.z, b0.z, b1.z, b2.z, b3.z, dC.z)
        LANE(3, q0.w, q1.w, q2.w, q3.w, b0.w, b1.w, b2.w, b3.w, dC.w)
        #undef LANE

        *(float4*)(&g_C[l][t][G0+eb][(half<<6) + es0]) =
            make_float4(nc[0], nc[1], nc[2], nc[3]);
        float* wdst = half ? &g_h[l][t][G0+eb][es0] : &g_o[l][t][G0+eb][es0];
        *(float4*)wdst = make_float4(wh[0], wh[1], wh[2], wh[3]);

        __threadfence();
        __syncthreads();
        if (tid == 0){
            if (half) *(volatile int*)&g_hf[l][g] = t + 1;
            else      *(volatile int*)&g_of[l][g] = t + 1;
        }
    }
}

// out[row][j] = sum_i (g_o[1][row][i] + g_o[3][row][i]) * Wa[j][i] + ba[j]
extern "C" __global__ void __launch_bounds__(256)
proj_kernel(const float* __restrict__ Wa, const float* __restrict__ ba,
            float* __restrict__ out)
{
    __shared__ float sWa[64*64];
    __shared__ float sba[64];
    for (int i = threadIdx.x; i < 4096; i += 256) sWa[i] = Wa[i];
    if (threadIdx.x < 64) sba[threadIdx.x] = ba[threadIdx.x];
    __syncthreads();

    int row = blockIdx.x * 256 + threadIdx.x;   // 0..65535 = t*256+b
    const float* p1 = &g_o[1][0][0][0] + (size_t)row * 64;
    const float* p3 = &g_o[3][0][0][0] + (size_t)row * 64;
    float v[64];
    #pragma unroll
    for (int i = 0; i < 64; i += 4){
        float4 a = *(const float4*)(p1 + i);
        float4 c = *(const float4*)(p3 + i);
        v[i+0] = a.x + c.x;  v[i+1] = a.y + c.y;
        v[i+2] = a.z + c.z;  v[i+3] = a.w + c.w;
    }
    float* orow = out + (size_t)row * 64;
    for (int j = 0; j < 64; ++j){
        float acc = sba[j];
        const float* wr = sWa + j*64;
        #pragma unroll
        for (int i = 0; i < 64; ++i) acc = fmaf(v[i], wr[i], acc);
        orow[j] = acc;
    }
}

extern "C" void kernel_launch(void* const* d_in, const int* in_sizes, int n_in,
                              void* d_out, int out_size)
{
    const float* x  = (const float*)d_in[0];
    const float* W  = (const float*)d_in[1];
    const float* b  = (const float*)d_in[2];
    const float* Wa = (const float*)d_in[3];
    const float* ba = (const float*)d_in[4];

    cudaFuncSetAttribute((const void*)rnn_kernel,
                         cudaFuncAttributeMaxDynamicSharedMemorySize, SMEM_BYTES);

    reset_kernel<<<1, 64>>>();
    rnn_kernel<<<128, 256, SMEM_BYTES>>>(x, W, b);
    proj_kernel<<<256, 256>>>(Wa, ba, (float*)d_out);
}

// round 3
// speedup vs baseline: 1.1378x; 1.1378x over previous
#include <cuda_runtime.h>

// DilatedSparseRnnStack on GB300 — v2: FFMA2 (fma.rn.f32x2) matvec with
// crossbar-minimal tiling (thread = 2 rows x 8 batches, batch-paired accums).
// 128 persistent CTAs = 4 layers x 2 column-halves x 16 batch-groups,
// weights resident in SMEM, cross-layer pipeline via global flags.

#define TT   256
#define BB   256
#define KD   192      // 64 x + 64 prevH + 64 dH
#define RH   256      // gate rows per half
#define BS   16       // batch per group
#define NG   16
#define GSTRIDE 18    // padded gate-scratch row stride (floats)
#define SMEM_FLOATS (KD*RH + RH + RH*GSTRIDE)
#define SMEM_BYTES  (SMEM_FLOATS * 4)

__device__ float g_h[4][TT][BB][64];
__device__ float g_C[4][TT][BB][128];
__device__ float g_o[4][TT][BB][64];
__device__ int   g_hf[4][NG];
__device__ int   g_of[4][NG];

__device__ __forceinline__ float sigm(float x){
    return __fdividef(1.f, 1.f + __expf(-x));
}
__device__ __forceinline__ float tanh_f(float x){
    float e = __expf(2.f * x);
    return 1.f - __fdividef(2.f, e + 1.f);
}
__device__ __forceinline__ void fma2(unsigned long long &acc,
                                     unsigned long long a, unsigned long long b){
    asm("fma.rn.f32x2 %0, %1, %2, %0;" : "+l"(acc) : "l"(a), "l"(b));
}
__device__ __forceinline__ unsigned long long dup2(float v){
    unsigned long long r; unsigned u = __float_as_uint(v);
    asm("mov.b64 %0, {%1, %1};" : "=l"(r) : "r"(u));
    return r;
}

extern "C" __global__ void reset_kernel(){
    int i = threadIdx.x;
    if (i < 4*NG){ ((int*)g_hf)[i] = 0; ((int*)g_of)[i] = 0; }
}

extern "C" __global__ void __launch_bounds__(256,1)
rnn_kernel(const float* __restrict__ X, const float* __restrict__ W,
           const float* __restrict__ Bv)
{
    extern __shared__ float sm[];
    float* sW = sm;                  // [k*256 + r] transposed weights
    float* sB = sm + KD*RH;          // [RH]
    float* sX = sB + RH;             // xh k-major: [k][16]  (3072 floats)
    float* sG = sX;                  // gates scratch [row][GSTRIDE] (reuses sX)

    const int tid  = threadIdx.x;
    const int bid  = blockIdx.x;
    const int l    = bid >> 5;
    const int half = (bid >> 4) & 1;
    const int g    = bid & 15;
    const int G0   = g * BS;
    const int d    = (l==0) ? 1 : ((l==1) ? 3 : ((l==2) ? 6 : 12));

    // load transposed weight half + bias
    const float* Wl = W + (size_t)l * 512 * KD;
    for (int idx = tid; idx < RH*KD; idx += 256){
        int r = idx / KD;
        int k = idx - r*KD;
        int grow = ((r>>6)<<7) + (half<<6) + (r&63);
        sW[k*RH + r] = Wl[(size_t)grow*KD + k];
    }
    {
        int grow = ((tid>>6)<<7) + (half<<6) + (tid&63);
        sB[tid] = Bv[l*512 + grow];
    }
    __syncthreads();

    // matvec tile: thread owns rows 2*rs, 2*rs+1 and batches b0..b0+7
    const int rs = tid & 127;
    const int b0 = (tid >> 7) * 8;
    // epilogue tile: thread owns batch eb, states s0..s0+3
    const int eb = tid & 15;
    const int s0 = (tid >> 4) << 2;

    float cP[4] = {0.f, 0.f, 0.f, 0.f};

    for (int t = 0; t < TT; ++t){
        if (tid == 0){
            if (l > 0){
                volatile int* fp = &g_of[l-1][g];
                while (*fp < t+1) {}
            }
            if (half == 0 && t > 0){
                volatile int* fp = &g_hf[l][g];
                while (*fp < t) {}
            }
            __threadfence();
        }
        __syncthreads();

        // ---- stage xh (k-major, [k][16]) ----
        const float* srcX = (l==0) ? (X + ((size_t)t*BB + G0)*64)
                                   : &g_o[l-1][t][G0][0];
        const float* srcP = (t > 0)  ? &g_h[l][t-1][G0][0] : (const float*)0;
        const float* srcD = (t >= d) ? &g_h[l][t-d][G0][0] : srcP;
        #pragma unroll
        for (int it = 0; it < 12; ++it){
            int idx = it*256 + tid;          // 0..3071
            int b   = idx & 15;
            int kk  = idx >> 4;              // 0..191
            int sec = kk >> 6;
            int c   = kk & 63;
            const float* s = (sec == 0) ? srcX : ((sec == 1) ? srcP : srcD);
            float v = s ? s[b*64 + c] : 0.f;
            sX[kk*16 + b] = v;               // conflict-free STS
        }
        __syncthreads();

        // ---- matvec: rows (2rs,2rs+1) x batches b0..b0+7, FFMA2 ----
        unsigned long long a00=0,a01=0,a02=0,a03=0;
        unsigned long long a10=0,a11=0,a12=0,a13=0;
        const float* wp = sW + rs*2;
        const float* xp = sX + b0;
        #pragma unroll 4
        for (int k = 0; k < KD; ++k){
            float2 w = *(const float2*)(wp + (k<<8));
            unsigned long long w0 = dup2(w.x);
            unsigned long long w1 = dup2(w.y);
            const ulonglong2* xq = (const ulonglong2*)(xp + (k<<4));
            ulonglong2 xa = xq[0];           // batches b0..b0+3
            ulonglong2 xb = xq[1];           // batches b0+4..b0+7
            fma2(a00, w0, xa.x); fma2(a01, w0, xa.y);
            fma2(a02, w0, xb.x); fma2(a03, w0, xb.y);
            fma2(a10, w1, xa.x); fma2(a11, w1, xa.y);
            fma2(a12, w1, xb.x); fma2(a13, w1, xb.y);
        }
        __syncthreads();   // sX fully consumed -> region becomes sG

        // gates scratch: sG[row][GSTRIDE], batch pairs stored as u64
        {
            unsigned long long* g0 = (unsigned long long*)(sG + (rs*2)*GSTRIDE + b0);
            unsigned long long* g1 = (unsigned long long*)(sG + (rs*2+1)*GSTRIDE + b0);
            g0[0]=a00; g0[1]=a01; g0[2]=a02; g0[3]=a03;
            g1[0]=a10; g1[1]=a11; g1[2]=a12; g1[3]=a13;
        }
        __syncthreads();

        // ---- elementwise gates + recurrence (batch eb, states s0..s0+3) ----
        float4 b0v = *(const float4*)(sB +         s0);
        float4 b1v = *(const float4*)(sB +  64  +  s0);
        float4 b2v = *(const float4*)(sB + 128  +  s0);
        float4 b3v = *(const float4*)(sB + 192  +  s0);
        float4 dC = make_float4(0.f, 0.f, 0.f, 0.f);
        if (t >= d) dC = *(const float4*)(&g_C[l][t-d][G0+eb][(half<<6) + s0]);

        float nc[4], wh[4];
        const float* dCp = &dC.x;
        const float* bp0 = &b0v.x; const float* bp1 = &b1v.x;
        const float* bp2 = &b2v.x; const float* bp3 = &b3v.x;
        #pragma unroll
        for (int i = 0; i < 4; ++i){
            int srow = s0 + i;
            float q0 = sG[(      srow)*GSTRIDE + eb];
            float q1 = sG[( 64 + srow)*GSTRIDE + eb];
            float q2 = sG[(128 + srow)*GSTRIDE + eb];
            float q3 = sG[(192 + srow)*GSTRIDE + eb];
            float f  = sigm(q0 + bp0[i] + 1.f);
            float ns = tanh_f(q1 + bp1[i]);
            float al = sigm(q2 + bp2[i]);
            float oo = sigm(q3 + bp3[i]);
            float wc = (t >= d) ? (al*cP[i] + (1.f-al)*dCp[i]) : cP[i];
            float c2 = (t > 0)  ? (f*wc + (1.f-f)*ns) : ns;
            nc[i] = c2; wh[i] = oo*c2; cP[i] = c2;
        }

        *(float4*)(&g_C[l][t][G0+eb][(half<<6) + s0]) =
            make_float4(nc[0], nc[1], nc[2], nc[3]);
        float* wdst = half ? &g_h[l][t][G0+eb][s0] : &g_o[l][t][G0+eb][s0];
        *(float4*)wdst = make_float4(wh[0], wh[1], wh[2], wh[3]);

        __threadfence();
        __syncthreads();
        if (tid == 0){
            if (half) *(volatile int*)&g_hf[l][g] = t + 1;
            else      *(volatile int*)&g_of[l][g] = t + 1;
        }
    }
}

// out[row][j] = sum_i (g_o[1][row][i] + g_o[3][row][i]) * Wa[j][i] + ba[j]
extern "C" __global__ void __launch_bounds__(256)
proj_kernel(const float* __restrict__ Wa, const float* __restrict__ ba,
            float* __restrict__ out)
{
    __shared__ float sWa[64*64];
    __shared__ float sba[64];
    for (int i = threadIdx.x; i < 4096; i += 256) sWa[i] = Wa[i];
    if (threadIdx.x < 64) sba[threadIdx.x] = ba[threadIdx.x];
    __syncthreads();

    int row = blockIdx.x * 256 + threadIdx.x;
    const float* p1 = &g_o[1][0][0][0] + (size_t)row * 64;
    const float* p3 = &g_o[3][0][0][0] + (size_t)row * 64;
    unsigned long long vp[32];
    #pragma unroll
    for (int i = 0; i < 64; i += 4){
        float4 a = *(const float4*)(p1 + i);
        float4 c = *(const float4*)(p3 + i);
        float2 lo = make_float2(a.x + c.x, a.y + c.y);
        float2 hi = make_float2(a.z + c.z, a.w + c.w);
        vp[i/2]   = *(unsigned long long*)&lo;
        vp[i/2+1] = *(unsigned long long*)&hi;
    }
    float* orow = out + (size_t)row * 64;
    for (int j = 0; j < 64; ++j){
        const unsigned long long* wr = (const unsigned long long*)(sWa + j*64);
        unsigned long long acc = 0ull;
        #pragma unroll
        for (int i = 0; i < 32; ++i) fma2(acc, vp[i], wr[i]);
        float2 af = *(float2*)&acc;
        orow[j] = af.x + af.y + sba[j];
    }
}

extern "C" void kernel_launch(void* const* d_in, const int* in_sizes, int n_in,
                              void* d_out, int out_size)
{
    const float* x  = (const float*)d_in[0];
    const float* W  = (const float*)d_in[1];
    const float* b  = (const float*)d_in[2];
    const float* Wa = (const float*)d_in[3];
    const float* ba = (const float*)d_in[4];

    cudaFuncSetAttribute((const void*)rnn_kernel,
                         cudaFuncAttributeMaxDynamicSharedMemorySize, SMEM_BYTES);

    reset_kernel<<<1, 64>>>();
    rnn_kernel<<<128, 256, SMEM_BYTES>>>(x, W, b);
    proj_kernel<<<256, 256>>>(Wa, ba, (float*)d_out);
}